// round 6
// baseline (speedup 1.0000x reference)
#include <cuda_runtime.h>
#include <math.h>

#define NROWS 524288
#define H 128
#define TPB 128

// level_data is a module-level constant of the problem:
//   [GRID_SIZE=100, N_GREEN=524288, N_RED=524288]; scale = 100^2 - 1 = 9999.
#define LD0 100.0f
#define LD1 524288.0f
#define LD2 524288.0f
#define SCALE_CONST 9999.0f

// ---------------------------------------------------------------------------
// Brute-force exact kernel: one thread per row. W2 read via __ldg (uniform
// address across the block -> L1 broadcast; 64KB resident). Output written as
// FLOAT32: value = (float)(int)(sigmoid(out/500)*9999). Integers <= 9999 are
// exactly representable in fp32.
// ---------------------------------------------------------------------------
__global__ void __launch_bounds__(TPB, 1) brute_kernel(
    const float* __restrict__ z,
    const float* __restrict__ gW1, const float* __restrict__ gb1,
    const float* __restrict__ gW2, const float* __restrict__ gb2,
    const float* __restrict__ gW3, const float* __restrict__ gb3,
    const float* __restrict__ rW1, const float* __restrict__ rb1,
    const float* __restrict__ rW2, const float* __restrict__ rb2,
    const float* __restrict__ rW3, const float* __restrict__ rb3,
    float* __restrict__ out)
{
    __shared__ float s_base[H], s_w[H], s_b2[H], s_w3[H];
    __shared__ float s_zext[16];
    __shared__ float s_b3;

    const int tid = threadIdx.x;
    const int mlp = blockIdx.y;
    const float* W1 = mlp ? rW1 : gW1;
    const float* b1 = mlp ? rb1 : gb1;
    const float* W2 = mlp ? rW2 : gW2;
    const float* b2 = mlp ? rb2 : gb2;
    const float* W3 = mlp ? rW3 : gW3;
    const float* b3p = mlp ? rb3 : gb3;

    if (tid < 10) s_zext[tid] = z[tid];
    if (tid == 10) s_zext[10] = LD0;
    if (tid == 11) s_zext[11] = LD1;
    if (tid == 12) s_zext[12] = LD2;
    if (tid == 13) s_b3 = b3p[0];
    __syncthreads();

    // Layer-1 affine form per unit: pre_j(i) = base_j + i * w_j (exact algebra:
    // the first 13 input features are constant across rows, only idx varies).
    {
        float b = b1[tid];
#pragma unroll
        for (int j = 0; j < 13; ++j) b = fmaf(W1[tid * 14 + j], s_zext[j], b);
        s_base[tid] = b;
        s_w[tid]    = W1[tid * 14 + 13];
        s_b2[tid]   = b2[tid];
        s_w3[tid]   = W3[tid];
    }
    __syncthreads();

    const float b3 = s_b3;
    const int row = blockIdx.x * TPB + tid;
    if (row >= NROWS) return;
    const float fi = (float)row;

    // Layer 1: h_j = leaky_relu(base_j + i*w_j, 0.2)
    float h[H];
#pragma unroll
    for (int j = 0; j < H; ++j) {
        float pre = fmaf(fi, s_w[j], s_base[j]);
        h[j] = fmaxf(pre, 0.2f * pre);
    }

    // Layer 2 (full 128x128) + ELU + Layer 3
    float a = 0.0f;
    const float4* W2v = (const float4*)W2;
    for (int k = 0; k < H; ++k) {
        float a0 = s_b2[k], a1 = 0.f, a2 = 0.f, a3 = 0.f;
#pragma unroll
        for (int jv = 0; jv < H / 4; ++jv) {
            float4 wv = __ldg(&W2v[(k << 5) + jv]);   // uniform: L1 broadcast
            a0 = fmaf(wv.x, h[4 * jv + 0], a0);
            a1 = fmaf(wv.y, h[4 * jv + 1], a1);
            a2 = fmaf(wv.z, h[4 * jv + 2], a2);
            a3 = fmaf(wv.w, h[4 * jv + 3], a3);
        }
        float x = (a0 + a1) + (a2 + a3);
        // elu(x): for x <= -20, expm1f(x) == -1 in fp32, so the max() is exact
        float e = fmaxf(x, -1.0f);
        if (x < 0.0f && x > -20.0f) e = expm1f(x);
        a = fmaf(s_w3[k], e, a);
    }

    float o = (a + b3) * (1.0f / 500.0f);
    float s = 1.0f / (1.0f + expf(-o));
    int coord = (int)(s * SCALE_CONST);          // truncation, as in reference
    out[mlp * NROWS + row] = (float)coord;       // FLOAT32 output
}

// ---------------------------------------------------------------------------
// Host: identify inputs by size signature; handle sizes expressed either as
// ELEMENT counts or as BYTES; fall back to positional dict order.
// ---------------------------------------------------------------------------
struct InMap {
    int z, gW1, gb1, gW2, gb2, gW3, gb3, rW1, rb1, rW2, rb2, rW3, rb3;
    bool ok;
};

static InMap scan_sizes(const int* in_sizes, int n_in, int unit /*1=elems,4=bytes*/)
{
    InMap m; m.ok = false;
    int i1792[2], n1792 = 0;
    int i16384[2], n16384 = 0;
    int i128[6], n128 = 0;
    int i1[2], n1 = 0;
    int iz = -1;

    const int S_W1 = 1792 * unit, S_W2 = 16384 * unit, S_128 = 128 * unit,
              S_1 = 1 * unit, S_Z = 10 * unit;

    for (int i = 0; i < n_in; ++i) {
        int s = in_sizes[i];
        if (s == S_W1 && n1792 < 2)        i1792[n1792++] = i;
        else if (s == S_W2 && n16384 < 2)  i16384[n16384++] = i;
        else if (s == S_128 && n128 < 6)   i128[n128++] = i;
        else if (s == S_1 && n1 < 2)       i1[n1++] = i;
        else if (s == S_Z && iz < 0)       iz = i;
    }
    if (n1792 != 2 || n16384 != 2 || n128 != 6 || n1 != 2 || iz < 0) return m;

    // g-MLP tensors precede r-MLP tensors in both dict and alphabetical
    // orders. Disambiguate the 128-class layout by position vs first W2:
    // dict  -> [gb1, gb2, gW3, ...] with gb1 before gW2
    // alpha -> [gW3, gb1, gb2, ...] with gW3 after gW2
    bool dict_order = i128[0] < i16384[0];

    m.z = iz;
    m.gW1 = i1792[0];  m.rW1 = i1792[1];
    m.gW2 = i16384[0]; m.rW2 = i16384[1];
    m.gb3 = i1[0];     m.rb3 = i1[1];
    if (dict_order) {
        m.gb1 = i128[0]; m.gb2 = i128[1]; m.gW3 = i128[2];
        m.rb1 = i128[3]; m.rb2 = i128[4]; m.rW3 = i128[5];
    } else {
        m.gW3 = i128[0]; m.gb1 = i128[1]; m.gb2 = i128[2];
        m.rW3 = i128[3]; m.rb1 = i128[4]; m.rb2 = i128[5];
    }
    m.ok = true;
    return m;
}

extern "C" void kernel_launch(void* const* d_in, const int* in_sizes, int n_in,
                              void* d_out, int out_size)
{
    InMap m = scan_sizes(in_sizes, n_in, 1);       // element counts
    if (!m.ok) m = scan_sizes(in_sizes, n_in, 4);  // byte counts
    if (!m.ok) {
        // Positional fallback: dict-insertion order
        // z level_data gW1 gb1 gW2 gb2 gW3 gb3 rW1 rb1 rW2 rb2 rW3 rb3
        m.z = 0;
        m.gW1 = 2;  m.gb1 = 3;  m.gW2 = 4;  m.gb2 = 5;  m.gW3 = 6;  m.gb3 = 7;
        m.rW1 = 8;  m.rb1 = 9;  m.rW2 = 10; m.rb2 = 11; m.rW3 = 12; m.rb3 = 13;
        m.ok = true;
    }

    const float* z   = (const float*)d_in[m.z];
    const float* gW1 = (const float*)d_in[m.gW1];
    const float* gb1 = (const float*)d_in[m.gb1];
    const float* gW2 = (const float*)d_in[m.gW2];
    const float* gb2 = (const float*)d_in[m.gb2];
    const float* gW3 = (const float*)d_in[m.gW3];
    const float* gb3 = (const float*)d_in[m.gb3];
    const float* rW1 = (const float*)d_in[m.rW1];
    const float* rb1 = (const float*)d_in[m.rb1];
    const float* rW2 = (const float*)d_in[m.rW2];
    const float* rb2 = (const float*)d_in[m.rb2];
    const float* rW3 = (const float*)d_in[m.rW3];
    const float* rb3 = (const float*)d_in[m.rb3];

    float* out = (float*)d_out;

    // Write the red half only if the buffer actually holds both outputs.
    int nmlp = (out_size >= 2 * NROWS) ? 2 : 1;

    brute_kernel<<<dim3(NROWS / TPB, nmlp), TPB>>>(
        z, gW1, gb1, gW2, gb2, gW3, gb3,
        rW1, rb1, rW2, rb2, rW3, rb3, out);
}

// round 7
// speedup vs baseline: 44.5486x; 44.5486x over previous
#include <cuda_runtime.h>
#include <math.h>

#define NROWS 524288
#define H 128
#define NSEG 129          // max intervals (128 breakpoints + 1)
#define NB (NSEG + 1)     // boundary entries B[0..129]
#define TPB 256
#define RPT 4

// level_data is a module-level constant of the problem:
//   [GRID_SIZE=100, N_GREEN=524288, N_RED=524288]; scale = 100^2-1 = 9999.
#define LD0 100.0f
#define LD1 524288.0f
#define LD2 524288.0f
#define SCALE_CONST 9999.0f

// Scratch (no allocations allowed): per-MLP, per-segment affine coefficients
// of the layer-2 preactivation: x_k(i) = c0[m][k] + i * c1[m][k]
__device__ float g_c0[2][NSEG][H];
__device__ float g_c1[2][NSEG][H];
__device__ int   g_B[2][NB];

// ---------------------------------------------------------------------------
// Prep kernel: grid (32, 2), 128 threads. blockIdx.y selects MLP.
// 1) layer-1 affine coefficients, 2) sorted integer breakpoints,
// 3) per-segment c0/c1 via two 128x128 GEMVs (W2 rows via __ldg, L1-resident).
// ---------------------------------------------------------------------------
__global__ void __launch_bounds__(H) prep_kernel(
    const float* __restrict__ z,
    const float* __restrict__ gW1, const float* __restrict__ gb1,
    const float* __restrict__ gW2, const float* __restrict__ gb2,
    const float* __restrict__ rW1, const float* __restrict__ rb1,
    const float* __restrict__ rW2, const float* __restrict__ rb2)
{
    __shared__ float s_zext[16];
    __shared__ float s_base[H], s_w[H], s_sb[H], s_sw[H];
    __shared__ int   s_bk[H];
    __shared__ int   s_B[NB];

    const int k   = threadIdx.x;
    const int mlp = blockIdx.y;
    const float* W1 = mlp ? rW1 : gW1;
    const float* b1 = mlp ? rb1 : gb1;
    const float* W2 = mlp ? rW2 : gW2;
    const float* b2 = mlp ? rb2 : gb2;

    if (k < 10) s_zext[k] = z[k];
    if (k == 10) s_zext[10] = LD0;
    if (k == 11) s_zext[11] = LD1;
    if (k == 12) s_zext[12] = LD2;
    __syncthreads();

    // Layer-1 affine form: pre_k(i) = base_k + i * w_k (exact: only idx varies)
    float b = b1[k];
#pragma unroll
    for (int j = 0; j < 13; ++j) b = fmaf(W1[k * 14 + j], s_zext[j], b);
    float w = W1[k * 14 + 13];
    s_base[k] = b;
    s_w[k]    = w;

    // Integer breakpoint where the LeakyReLU sign flips (sentinel NROWS if none)
    int bk = NROWS;
    if (w != 0.0f) {
        float t = -b / w;
        if (t > 0.0f && t < (float)NROWS) {
            bk = (int)ceilf(t);
            if (bk < 1) bk = 1;
            if (bk > NROWS) bk = NROWS;
        }
    }
    s_bk[k] = bk;
    __syncthreads();

    // Rank sort (O(128) per thread) -> sorted boundary list
    int r = 0;
#pragma unroll 8
    for (int j = 0; j < H; ++j) {
        int v = s_bk[j];
        r += (v < bk) || (v == bk && j < k);
    }
    if (k == 0) { s_B[0] = 0; s_B[NB - 1] = NROWS; }
    s_B[1 + r] = bk;
    __syncthreads();

    if (blockIdx.x == 0) {
        for (int q = k; q < NB; q += H) g_B[mlp][q] = s_B[q];
    }

    const float4* W2v = (const float4*)(W2 + k * H);  // this thread's W2 row
    const float myb2 = b2[k];

    for (int m = blockIdx.x; m < NSEG; m += gridDim.x) {
        int s0 = s_B[m], s1 = s_B[m + 1];      // uniform across block
        __syncthreads();                       // protect s_sb/s_sw reuse
        if (s0 < s1) {
            // slope of leaky_relu is constant within the segment; use i=s0
            float pre = fmaf((float)s0, s_w[k], s_base[k]);
            float sl  = (pre >= 0.0f) ? 1.0f : 0.2f;
            s_sb[k] = sl * s_base[k];
            s_sw[k] = sl * s_w[k];
        }
        __syncthreads();
        if (s0 < s1) {
            float c0 = myb2, c1 = 0.0f;
#pragma unroll 4
            for (int jv = 0; jv < H / 4; ++jv) {
                float4 wv = __ldg(&W2v[jv]);
                int j = jv * 4;
                c0 = fmaf(wv.x, s_sb[j + 0], c0);  c1 = fmaf(wv.x, s_sw[j + 0], c1);
                c0 = fmaf(wv.y, s_sb[j + 1], c0);  c1 = fmaf(wv.y, s_sw[j + 1], c1);
                c0 = fmaf(wv.z, s_sb[j + 2], c0);  c1 = fmaf(wv.z, s_sw[j + 2], c1);
                c0 = fmaf(wv.w, s_sb[j + 3], c0);  c1 = fmaf(wv.w, s_sw[j + 3], c1);
            }
            g_c0[mlp][m][k] = c0;
            g_c1[mlp][m][k] = c1;
        }
    }
}

// ---------------------------------------------------------------------------
// Main kernel: grid (512, 2), 256 threads, 4 rows/thread (1024 rows/block).
// Per row: out = sum_k w3_k * elu(c0_k + i*c1_k) + b3;
//          coord = (float)(int)(sigmoid(out/500) * 9999)
// ELU fast path: elu(x) == fmaxf(x,-1) exactly (fp32) outside (-20,0);
// a conservative guard takes the rare expm1f branch inside the window.
// ---------------------------------------------------------------------------
__global__ void __launch_bounds__(TPB) main_kernel(
    const float* __restrict__ gW3, const float* __restrict__ gb3,
    const float* __restrict__ rW3, const float* __restrict__ rb3,
    float* __restrict__ out)
{
    __shared__ float s_c0[H], s_c1[H], s_w3[H];
    __shared__ int   s_B[NB];
    __shared__ float s_b3;

    const int tid = threadIdx.x;
    const int mlp = blockIdx.y;

    if (tid < H) s_w3[tid] = (mlp ? rW3 : gW3)[tid];
    for (int q = tid; q < NB; q += TPB) s_B[q] = g_B[mlp][q];
    if (tid == 0) s_b3 = (mlp ? rb3 : gb3)[0];
    __syncthreads();

    const int r0   = blockIdx.x * (TPB * RPT);
    const int rend = r0 + TPB * RPT;
    const int i0   = r0 + tid * RPT;
    const float fi0 = (float)i0, fi1 = fi0 + 1.0f, fi2 = fi0 + 2.0f, fi3 = fi0 + 3.0f;
    const float b3 = s_b3;
    float* outp = out + mlp * NROWS;

    int cur = 0;
    while (cur < NB - 2 && s_B[cur + 1] <= r0) ++cur;   // block-uniform

    int segS = r0;
    while (segS < rend) {
        while (cur < NB - 2 && s_B[cur + 1] <= segS) ++cur;  // skip empty segs
        int segE = min(s_B[cur + 1], rend);
        if (segE <= segS) segE = rend;                       // safety

        __syncthreads();                        // previous segment's reads done
        if (tid < H)            s_c0[tid]     = g_c0[mlp][cur][tid];
        else if (tid < 2 * H)   s_c1[tid - H] = g_c1[mlp][cur][tid - H];
        __syncthreads();

        if (i0 < segE && i0 + RPT > segS) {
            float a0 = 0.f, a1 = 0.f, a2 = 0.f, a3 = 0.f;
#pragma unroll 8
            for (int k = 0; k < H; ++k) {
                const float c0 = s_c0[k], c1 = s_c1[k], wk = s_w3[k];
                float x0 = fmaf(fi0, c1, c0);
                float x1 = fmaf(fi1, c1, c0);
                float x2 = fmaf(fi2, c1, c0);
                float x3 = fmaf(fi3, c1, c0);
                float e0 = fmaxf(x0, -1.0f);
                float e1 = fmaxf(x1, -1.0f);
                float e2 = fmaxf(x2, -1.0f);
                float e3 = fmaxf(x3, -1.0f);
                // Slow-path window: any x_j in (-20, 0)? x_j = x0 + j*c1
                // (up to rounding), so |x_j - x0| <= 3|c1| + eps.
                float th = fmaf(3.0f, fabsf(c1), 10.5f);
                if (fabsf(x0 + 10.0f) < th) {    // rare
                    if (x0 < 0.f && x0 > -20.f) e0 = expm1f(x0);
                    if (x1 < 0.f && x1 > -20.f) e1 = expm1f(x1);
                    if (x2 < 0.f && x2 > -20.f) e2 = expm1f(x2);
                    if (x3 < 0.f && x3 > -20.f) e3 = expm1f(x3);
                }
                a0 = fmaf(wk, e0, a0);
                a1 = fmaf(wk, e1, a1);
                a2 = fmaf(wk, e2, a2);
                a3 = fmaf(wk, e3, a3);
            }

            // Epilogue: sigmoid((a+b3)/500) * 9999, truncate, store as float
            float o0 = (a0 + b3) * (1.0f / 500.0f);
            float o1 = (a1 + b3) * (1.0f / 500.0f);
            float o2 = (a2 + b3) * (1.0f / 500.0f);
            float o3 = (a3 + b3) * (1.0f / 500.0f);
            float v0 = (float)(int)((1.0f / (1.0f + expf(-o0))) * SCALE_CONST);
            float v1 = (float)(int)((1.0f / (1.0f + expf(-o1))) * SCALE_CONST);
            float v2 = (float)(int)((1.0f / (1.0f + expf(-o2))) * SCALE_CONST);
            float v3 = (float)(int)((1.0f / (1.0f + expf(-o3))) * SCALE_CONST);

            if (i0 >= segS && i0 + RPT <= segE) {
                *(float4*)(outp + i0) = make_float4(v0, v1, v2, v3);
            } else {
                if (i0 + 0 >= segS && i0 + 0 < segE) outp[i0 + 0] = v0;
                if (i0 + 1 >= segS && i0 + 1 < segE) outp[i0 + 1] = v1;
                if (i0 + 2 >= segS && i0 + 2 < segE) outp[i0 + 2] = v2;
                if (i0 + 3 >= segS && i0 + 3 < segE) outp[i0 + 3] = v3;
            }
        }
        segS = segE;
    }
}

// ---------------------------------------------------------------------------
// Host: size-signature input scan (elements, then bytes, then positional).
// ---------------------------------------------------------------------------
struct InMap {
    int z, gW1, gb1, gW2, gb2, gW3, gb3, rW1, rb1, rW2, rb2, rW3, rb3;
    bool ok;
};

static InMap scan_sizes(const int* in_sizes, int n_in, int unit)
{
    InMap m; m.ok = false;
    int i1792[2], n1792 = 0;
    int i16384[2], n16384 = 0;
    int i128[6], n128 = 0;
    int i1[2], n1 = 0;
    int iz = -1;

    const int S_W1 = 1792 * unit, S_W2 = 16384 * unit, S_128 = 128 * unit,
              S_1 = 1 * unit, S_Z = 10 * unit;

    for (int i = 0; i < n_in; ++i) {
        int s = in_sizes[i];
        if (s == S_W1 && n1792 < 2)        i1792[n1792++] = i;
        else if (s == S_W2 && n16384 < 2)  i16384[n16384++] = i;
        else if (s == S_128 && n128 < 6)   i128[n128++] = i;
        else if (s == S_1 && n1 < 2)       i1[n1++] = i;
        else if (s == S_Z && iz < 0)       iz = i;
    }
    if (n1792 != 2 || n16384 != 2 || n128 != 6 || n1 != 2 || iz < 0) return m;

    bool dict_order = i128[0] < i16384[0];

    m.z = iz;
    m.gW1 = i1792[0];  m.rW1 = i1792[1];
    m.gW2 = i16384[0]; m.rW2 = i16384[1];
    m.gb3 = i1[0];     m.rb3 = i1[1];
    if (dict_order) {
        m.gb1 = i128[0]; m.gb2 = i128[1]; m.gW3 = i128[2];
        m.rb1 = i128[3]; m.rb2 = i128[4]; m.rW3 = i128[5];
    } else {
        m.gW3 = i128[0]; m.gb1 = i128[1]; m.gb2 = i128[2];
        m.rW3 = i128[3]; m.rb1 = i128[4]; m.rb2 = i128[5];
    }
    m.ok = true;
    return m;
}

extern "C" void kernel_launch(void* const* d_in, const int* in_sizes, int n_in,
                              void* d_out, int out_size)
{
    InMap m = scan_sizes(in_sizes, n_in, 1);
    if (!m.ok) m = scan_sizes(in_sizes, n_in, 4);
    if (!m.ok) {
        m.z = 0;
        m.gW1 = 2;  m.gb1 = 3;  m.gW2 = 4;  m.gb2 = 5;  m.gW3 = 6;  m.gb3 = 7;
        m.rW1 = 8;  m.rb1 = 9;  m.rW2 = 10; m.rb2 = 11; m.rW3 = 12; m.rb3 = 13;
    }

    const float* z   = (const float*)d_in[m.z];
    const float* gW1 = (const float*)d_in[m.gW1];
    const float* gb1 = (const float*)d_in[m.gb1];
    const float* gW2 = (const float*)d_in[m.gW2];
    const float* gb2 = (const float*)d_in[m.gb2];
    const float* gW3 = (const float*)d_in[m.gW3];
    const float* gb3 = (const float*)d_in[m.gb3];
    const float* rW1 = (const float*)d_in[m.rW1];
    const float* rb1 = (const float*)d_in[m.rb1];
    const float* rW2 = (const float*)d_in[m.rW2];
    const float* rb2 = (const float*)d_in[m.rb2];
    const float* rW3 = (const float*)d_in[m.rW3];
    const float* rb3 = (const float*)d_in[m.rb3];

    float* out = (float*)d_out;
    int nmlp = (out_size >= 2 * NROWS) ? 2 : 1;

    prep_kernel<<<dim3(32, 2), H>>>(z, gW1, gb1, gW2, gb2,
                                    rW1, rb1, rW2, rb2);
    main_kernel<<<dim3(NROWS / (TPB * RPT), nmlp), TPB>>>(gW3, gb3, rW3, rb3, out);
}

// round 8
// speedup vs baseline: 88.1450x; 1.9786x over previous
#include <cuda_runtime.h>
#include <math.h>

#define NROWS 524288
#define H 128
#define NSEG 129          // max segments (128 layer-1 breakpoints + 1)
#define NB (NSEG + 1)     // boundary entries B[0..129]
#define TPB 256
#define RPT 8
#define PREP_GRID 64

// level_data is a module-level constant of the problem:
//   [GRID_SIZE=100, N_GREEN=524288, N_RED=524288]; scale = 100^2-1 = 9999.
#define LD0 100.0f
#define LD1 524288.0f
#define LD2 524288.0f
#define SCALE_CONST 9999.0f
#define NEG_CUT -18.0f    // expm1f(x) == -1.0f exactly (fp32) for x <= -18

// Per-MLP, per-segment data (device globals: no allocations allowed)
__device__ float g_A0[2][NSEG];          // folded affine part: sum wk*x (+ sum -wk)
__device__ float g_A1[2][NSEG];
__device__ int   g_nact[2][NSEG];        // # active (non-foldable) units
__device__ float g_ac0[2][NSEG][H];      // active-unit coefficients
__device__ float g_ac1[2][NSEG][H];
__device__ float g_awk[2][NSEG][H];
__device__ int   g_B[2][NB];             // segment boundaries

// ---------------------------------------------------------------------------
// Prep kernel: grid (PREP_GRID, 2), 128 threads. blockIdx.y selects MLP.
// 1) layer-1 affine coefficients  2) sorted breakpoints -> segments
// 3) per-segment c0/c1 (two 128x128 GEMVs)  4) regime classification:
//    fold linear/saturated units into (A0, A1); compact the rest.
// ---------------------------------------------------------------------------
__global__ void __launch_bounds__(H) prep_kernel(
    const float* __restrict__ z,
    const float* __restrict__ gW1, const float* __restrict__ gb1,
    const float* __restrict__ gW2, const float* __restrict__ gb2,
    const float* __restrict__ gW3,
    const float* __restrict__ rW1, const float* __restrict__ rb1,
    const float* __restrict__ rW2, const float* __restrict__ rb2,
    const float* __restrict__ rW3)
{
    __shared__ float s_zext[16];
    __shared__ float s_base[H], s_w[H], s_sb[H], s_sw[H];
    __shared__ float s_cA0[H], s_cA1[H];
    __shared__ int   s_bk[H], s_act[H], s_rank[H];
    __shared__ int   s_B[NB];

    const int k   = threadIdx.x;
    const int mlp = blockIdx.y;
    const float* W1 = mlp ? rW1 : gW1;
    const float* b1 = mlp ? rb1 : gb1;
    const float* W2 = mlp ? rW2 : gW2;
    const float* b2 = mlp ? rb2 : gb2;
    const float* W3 = mlp ? rW3 : gW3;

    if (k < 10) s_zext[k] = z[k];
    if (k == 10) s_zext[10] = LD0;
    if (k == 11) s_zext[11] = LD1;
    if (k == 12) s_zext[12] = LD2;
    __syncthreads();

    // Layer-1 affine form: pre_k(i) = base_k + i * w_k (exact: only idx varies)
    float b = b1[k];
#pragma unroll
    for (int j = 0; j < 13; ++j) b = fmaf(W1[k * 14 + j], s_zext[j], b);
    float w = W1[k * 14 + 13];
    s_base[k] = b;
    s_w[k]    = w;

    // Integer breakpoint where LeakyReLU's slope flips (sentinel NROWS)
    int bk = NROWS;
    if (w != 0.0f) {
        float t = -b / w;
        if (t > 0.0f && t < (float)NROWS) {
            bk = (int)ceilf(t);
            if (bk < 1) bk = 1;
            if (bk > NROWS) bk = NROWS;
        }
    }
    s_bk[k] = bk;
    __syncthreads();

    // Rank sort -> sorted boundary list
    int r = 0;
#pragma unroll 8
    for (int j = 0; j < H; ++j) {
        int v = s_bk[j];
        r += (v < bk) || (v == bk && j < k);
    }
    if (k == 0) { s_B[0] = 0; s_B[NB - 1] = NROWS; }
    s_B[1 + r] = bk;
    __syncthreads();

    if (blockIdx.x == 0) {
        for (int q = k; q < NB; q += H) g_B[mlp][q] = s_B[q];
    }

    const float4* W2v = (const float4*)(W2 + k * H);  // this thread's W2 row
    const float myb2 = b2[k];
    const float wk   = W3[k];

    for (int m = blockIdx.x; m < NSEG; m += PREP_GRID) {
        const int s0 = s_B[m], s1 = s_B[m + 1];   // block-uniform
        const bool live = (s0 < s1);

        __syncthreads();                           // protect reused shared
        if (live) {
            // leaky_relu slope is constant within the segment; probe i=s0
            float pre = fmaf((float)s0, s_w[k], s_base[k]);
            float sl  = (pre >= 0.0f) ? 1.0f : 0.2f;
            s_sb[k] = sl * s_base[k];
            s_sw[k] = sl * s_w[k];
        }
        __syncthreads();

        float c0 = myb2, c1 = 0.0f;
        int active = 0;
        if (live) {
#pragma unroll 4
            for (int jv = 0; jv < H / 4; ++jv) {
                float4 wv = __ldg(&W2v[jv]);
                int j = jv * 4;
                c0 = fmaf(wv.x, s_sb[j + 0], c0);  c1 = fmaf(wv.x, s_sw[j + 0], c1);
                c0 = fmaf(wv.y, s_sb[j + 1], c0);  c1 = fmaf(wv.y, s_sw[j + 1], c1);
                c0 = fmaf(wv.z, s_sb[j + 2], c0);  c1 = fmaf(wv.z, s_sw[j + 2], c1);
                c0 = fmaf(wv.w, s_sb[j + 3], c0);  c1 = fmaf(wv.w, s_sw[j + 3], c1);
            }
            // Classify over i in [s0, s1-1]: x(i)=RN(c0+i*c1) is monotone in i,
            // so endpoint evaluations (same fmaf) bound the range exactly.
            float xa = fmaf((float)s0, c1, c0);
            float xb = fmaf((float)(s1 - 1), c1, c0);
            float lo = fminf(xa, xb), hi = fmaxf(xa, xb);
            bool lin = (lo >= 0.0f);          // elu(x)=x exactly
            bool neg = (hi <= NEG_CUT);       // elu(x)=-1 exactly in fp32
            active = (!lin && !neg) ? 1 : 0;
            s_cA0[k] = lin ? wk * c0 : (neg ? -wk : 0.0f);
            s_cA1[k] = lin ? wk * c1 : 0.0f;
            s_act[k] = active;
        }
        __syncthreads();

        if (live && k == 0) {
            // Deterministic fixed-order fold + exclusive prefix ranks
            float A0 = 0.0f, A1 = 0.0f;
            int n = 0;
#pragma unroll 8
            for (int j = 0; j < H; ++j) {
                A0 += s_cA0[j];
                A1 += s_cA1[j];
                s_rank[j] = n;
                n += s_act[j];
            }
            g_A0[mlp][m] = A0;
            g_A1[mlp][m] = A1;
            g_nact[mlp][m] = n;
        }
        __syncthreads();

        if (live && active) {
            int idx = s_rank[k];
            g_ac0[mlp][m][idx] = c0;
            g_ac1[mlp][m][idx] = c1;
            g_awk[mlp][m][idx] = wk;
        }
    }
}

// ---------------------------------------------------------------------------
// Main kernel: grid (NROWS/(TPB*RPT), 2), 256 threads, 8 rows/thread.
// Per row: o = A0 + i*A1 + sum_{active j} wk_j * elu(c0_j + i*c1_j) + b3
//          coord = (float)(int)(sigmoid(o/500) * 9999)
// ---------------------------------------------------------------------------
__global__ void __launch_bounds__(TPB) main_kernel(
    const float* __restrict__ gb3, const float* __restrict__ rb3,
    float* __restrict__ out)
{
    __shared__ float s_ac0[H], s_ac1[H], s_awk[H];
    __shared__ int   s_B[NB];
    __shared__ float s_A0, s_A1, s_b3;
    __shared__ int   s_nact;

    const int tid = threadIdx.x;
    const int mlp = blockIdx.y;

    for (int q = tid; q < NB; q += TPB) s_B[q] = g_B[mlp][q];
    if (tid == 0) s_b3 = (mlp ? rb3 : gb3)[0];
    __syncthreads();

    const int r0   = blockIdx.x * (TPB * RPT);
    const int rend = r0 + TPB * RPT;
    const int i0   = r0 + tid * RPT;
    const float fi0 = (float)i0;
    const float b3 = s_b3;
    float* outp = out + mlp * NROWS;

    int cur = 0;
    while (cur < NB - 2 && s_B[cur + 1] <= r0) ++cur;   // block-uniform

    int segS = r0;
    while (segS < rend) {
        while (cur < NB - 2 && s_B[cur + 1] <= segS) ++cur;  // skip empty segs
        int segE = min(s_B[cur + 1], rend);
        if (segE <= segS) segE = rend;                       // safety

        __syncthreads();                     // previous segment reads done
        if (tid == 0) {
            s_A0 = g_A0[mlp][cur];
            s_A1 = g_A1[mlp][cur];
            s_nact = g_nact[mlp][cur];
        }
        if (tid < H) {                       // load full list; extra is unread
            s_ac0[tid] = g_ac0[mlp][cur][tid];
            s_ac1[tid] = g_ac1[mlp][cur][tid];
            s_awk[tid] = g_awk[mlp][cur][tid];
        }
        __syncthreads();

        const float A0 = s_A0, A1 = s_A1;
        const int nact = s_nact;             // block-uniform -> no divergence

        if (i0 < segE && i0 + RPT > segS) {
            float v[RPT];
#pragma unroll
            for (int rr = 0; rr < RPT; ++rr) {
                const float fi = fi0 + (float)rr;
                float o = fmaf(fi, A1, A0);
                for (int j = 0; j < nact; ++j) {
                    float x = fmaf(fi, s_ac1[j], s_ac0[j]);
                    float e = fmaxf(x, -1.0f);
                    if (x < 0.0f && x > NEG_CUT) e = expm1f(x);
                    o = fmaf(s_awk[j], e, o);
                }
                o = (o + b3) * (1.0f / 500.0f);
                float sg = 1.0f / (1.0f + __expf(-o));
                v[rr] = (float)(int)(sg * SCALE_CONST);
            }

            if (i0 >= segS && i0 + RPT <= segE) {
                *(float4*)(outp + i0)     = make_float4(v[0], v[1], v[2], v[3]);
                *(float4*)(outp + i0 + 4) = make_float4(v[4], v[5], v[6], v[7]);
            } else {
#pragma unroll
                for (int rr = 0; rr < RPT; ++rr) {
                    int ii = i0 + rr;
                    if (ii >= segS && ii < segE) outp[ii] = v[rr];
                }
            }
        }
        segS = segE;
    }
}

// ---------------------------------------------------------------------------
// Host: size-signature input scan (elements, then bytes, then positional).
// ---------------------------------------------------------------------------
struct InMap {
    int z, gW1, gb1, gW2, gb2, gW3, gb3, rW1, rb1, rW2, rb2, rW3, rb3;
    bool ok;
};

static InMap scan_sizes(const int* in_sizes, int n_in, int unit)
{
    InMap m; m.ok = false;
    int i1792[2], n1792 = 0;
    int i16384[2], n16384 = 0;
    int i128[6], n128 = 0;
    int i1[2], n1 = 0;
    int iz = -1;

    const int S_W1 = 1792 * unit, S_W2 = 16384 * unit, S_128 = 128 * unit,
              S_1 = 1 * unit, S_Z = 10 * unit;

    for (int i = 0; i < n_in; ++i) {
        int s = in_sizes[i];
        if (s == S_W1 && n1792 < 2)        i1792[n1792++] = i;
        else if (s == S_W2 && n16384 < 2)  i16384[n16384++] = i;
        else if (s == S_128 && n128 < 6)   i128[n128++] = i;
        else if (s == S_1 && n1 < 2)       i1[n1++] = i;
        else if (s == S_Z && iz < 0)       iz = i;
    }
    if (n1792 != 2 || n16384 != 2 || n128 != 6 || n1 != 2 || iz < 0) return m;

    bool dict_order = i128[0] < i16384[0];

    m.z = iz;
    m.gW1 = i1792[0];  m.rW1 = i1792[1];
    m.gW2 = i16384[0]; m.rW2 = i16384[1];
    m.gb3 = i1[0];     m.rb3 = i1[1];
    if (dict_order) {
        m.gb1 = i128[0]; m.gb2 = i128[1]; m.gW3 = i128[2];
        m.rb1 = i128[3]; m.rb2 = i128[4]; m.rW3 = i128[5];
    } else {
        m.gW3 = i128[0]; m.gb1 = i128[1]; m.gb2 = i128[2];
        m.rW3 = i128[3]; m.rb1 = i128[4]; m.rb2 = i128[5];
    }
    m.ok = true;
    return m;
}

extern "C" void kernel_launch(void* const* d_in, const int* in_sizes, int n_in,
                              void* d_out, int out_size)
{
    InMap m = scan_sizes(in_sizes, n_in, 1);
    if (!m.ok) m = scan_sizes(in_sizes, n_in, 4);
    if (!m.ok) {
        m.z = 0;
        m.gW1 = 2;  m.gb1 = 3;  m.gW2 = 4;  m.gb2 = 5;  m.gW3 = 6;  m.gb3 = 7;
        m.rW1 = 8;  m.rb1 = 9;  m.rW2 = 10; m.rb2 = 11; m.rW3 = 12; m.rb3 = 13;
    }

    const float* z   = (const float*)d_in[m.z];
    const float* gW1 = (const float*)d_in[m.gW1];
    const float* gb1 = (const float*)d_in[m.gb1];
    const float* gW2 = (const float*)d_in[m.gW2];
    const float* gb2 = (const float*)d_in[m.gb2];
    const float* gW3 = (const float*)d_in[m.gW3];
    const float* gb3 = (const float*)d_in[m.gb3];
    const float* rW1 = (const float*)d_in[m.rW1];
    const float* rb1 = (const float*)d_in[m.rb1];
    const float* rW2 = (const float*)d_in[m.rW2];
    const float* rb2 = (const float*)d_in[m.rb2];
    const float* rW3 = (const float*)d_in[m.rW3];
    const float* rb3 = (const float*)d_in[m.rb3];

    float* out = (float*)d_out;
    int nmlp = (out_size >= 2 * NROWS) ? 2 : 1;

    prep_kernel<<<dim3(PREP_GRID, 2), H>>>(z, gW1, gb1, gW2, gb2, gW3,
                                           rW1, rb1, rW2, rb2, rW3);
    main_kernel<<<dim3(NROWS / (TPB * RPT), nmlp), TPB>>>(gb3, rb3, out);
}

// round 9
// speedup vs baseline: 96.2250x; 1.0917x over previous
#include <cuda_runtime.h>
#include <math.h>

#define NROWS 524288
#define H 128
#define NSEG 129          // max segments (128 layer-1 breakpoints + 1)
#define NB (NSEG + 1)     // boundary entries B[0..129]
#define TPB 256
#define RPT 8
#define PREP_GRID 64

// level_data is a module-level constant of the problem:
//   [GRID_SIZE=100, N_GREEN=524288, N_RED=524288]; scale = 100^2-1 = 9999.
#define LD0 100.0f
#define LD1 524288.0f
#define LD2 524288.0f
#define SCALE_CONST 9999.0f
#define NEG_CUT -18.0f    // expm1f(x) == -1.0f exactly (fp32) for x <= -18

// Per-MLP, per-segment data (device globals: no allocations allowed)
__device__ float g_A0[2][NSEG];          // folded affine part
__device__ float g_A1[2][NSEG];
__device__ int   g_nact[2][NSEG];        // # active (non-foldable) units
__device__ int   g_isfill[2][NSEG];      // 1 -> constant segment
__device__ float g_fill[2][NSEG];        // the constant coord value
__device__ float g_ac0[2][NSEG][H];      // active-unit coefficients
__device__ float g_ac1[2][NSEG][H];
__device__ float g_awk[2][NSEG][H];
__device__ int   g_B[2][NB];             // segment boundaries

// Shared epilogue — MUST be the identical instruction sequence in prep & main
__device__ __forceinline__ float coord_of(float o, float b3) {
    float t = (o + b3) * (1.0f / 500.0f);
    float sg = 1.0f / (1.0f + __expf(-t));
    return (float)(int)(sg * SCALE_CONST);
}

// ---------------------------------------------------------------------------
// Prep kernel: grid (PREP_GRID, 2), 128 threads. blockIdx.y selects MLP.
// ---------------------------------------------------------------------------
__global__ void __launch_bounds__(H) prep_kernel(
    const float* __restrict__ z,
    const float* __restrict__ gW1, const float* __restrict__ gb1,
    const float* __restrict__ gW2, const float* __restrict__ gb2,
    const float* __restrict__ gW3, const float* __restrict__ gb3,
    const float* __restrict__ rW1, const float* __restrict__ rb1,
    const float* __restrict__ rW2, const float* __restrict__ rb2,
    const float* __restrict__ rW3, const float* __restrict__ rb3)
{
    __shared__ float s_zext[16];
    __shared__ float s_base[H], s_w[H], s_sb[H], s_sw[H];
    __shared__ float s_wA0[4], s_wA1[4];
    __shared__ int   s_wn[4];
    __shared__ int   s_bk[H];
    __shared__ int   s_B[NB];

    const int k    = threadIdx.x;
    const int lane = k & 31;
    const int wid  = k >> 5;
    const int mlp  = blockIdx.y;
    const float* W1 = mlp ? rW1 : gW1;
    const float* b1 = mlp ? rb1 : gb1;
    const float* W2 = mlp ? rW2 : gW2;
    const float* b2 = mlp ? rb2 : gb2;
    const float* W3 = mlp ? rW3 : gW3;
    const float  b3 = (mlp ? rb3 : gb3)[0];

    if (k < 10) s_zext[k] = z[k];
    if (k == 10) s_zext[10] = LD0;
    if (k == 11) s_zext[11] = LD1;
    if (k == 12) s_zext[12] = LD2;
    __syncthreads();

    // Layer-1 affine form: pre_k(i) = base_k + i * w_k (exact: only idx varies)
    float b = b1[k];
#pragma unroll
    for (int j = 0; j < 13; ++j) b = fmaf(W1[k * 14 + j], s_zext[j], b);
    float w = W1[k * 14 + 13];
    s_base[k] = b;
    s_w[k]    = w;

    // Integer breakpoint where LeakyReLU's slope flips (sentinel NROWS)
    int bk = NROWS;
    if (w != 0.0f) {
        float t = -b / w;
        if (t > 0.0f && t < (float)NROWS) {
            bk = (int)ceilf(t);
            if (bk < 1) bk = 1;
            if (bk > NROWS) bk = NROWS;
        }
    }
    s_bk[k] = bk;
    __syncthreads();

    // Rank sort -> sorted boundary list
    int r = 0;
#pragma unroll 8
    for (int j = 0; j < H; ++j) {
        int v = s_bk[j];
        r += (v < bk) || (v == bk && j < k);
    }
    if (k == 0) { s_B[0] = 0; s_B[NB - 1] = NROWS; }
    s_B[1 + r] = bk;
    __syncthreads();

    if (blockIdx.x == 0) {
        for (int q = k; q < NB; q += H) g_B[mlp][q] = s_B[q];
    }

    const float4* W2v = (const float4*)(W2 + k * H);  // this thread's W2 row
    const float myb2 = b2[k];
    const float wk   = W3[k];

    for (int m = blockIdx.x; m < NSEG; m += PREP_GRID) {
        const int s0 = s_B[m], s1 = s_B[m + 1];   // block-uniform
        const bool live = (s0 < s1);

        __syncthreads();                           // protect reused shared
        if (live) {
            // leaky_relu slope is constant within the segment; probe i=s0
            float pre = fmaf((float)s0, s_w[k], s_base[k]);
            float sl  = (pre >= 0.0f) ? 1.0f : 0.2f;
            s_sb[k] = sl * s_base[k];
            s_sw[k] = sl * s_w[k];
        }
        __syncthreads();
        if (!live) continue;

        float c0 = myb2, c1 = 0.0f;
#pragma unroll 4
        for (int jv = 0; jv < H / 4; ++jv) {
            float4 wv = __ldg(&W2v[jv]);
            int j = jv * 4;
            c0 = fmaf(wv.x, s_sb[j + 0], c0);  c1 = fmaf(wv.x, s_sw[j + 0], c1);
            c0 = fmaf(wv.y, s_sb[j + 1], c0);  c1 = fmaf(wv.y, s_sw[j + 1], c1);
            c0 = fmaf(wv.z, s_sb[j + 2], c0);  c1 = fmaf(wv.z, s_sw[j + 2], c1);
            c0 = fmaf(wv.w, s_sb[j + 3], c0);  c1 = fmaf(wv.w, s_sw[j + 3], c1);
        }
        // Classify over i in [s0, s1-1]: x(i)=RN(c0+i*c1) is monotone in i.
        float xa = fmaf((float)s0, c1, c0);
        float xb = fmaf((float)(s1 - 1), c1, c0);
        float lo = fminf(xa, xb), hi = fmaxf(xa, xb);
        bool lin = (lo >= 0.0f);          // elu(x)=x exactly
        bool neg = (hi <= NEG_CUT);       // elu(x)=-1 exactly in fp32
        int active = (!lin && !neg) ? 1 : 0;

        float cA0 = lin ? wk * c0 : (neg ? -wk : 0.0f);
        float cA1 = lin ? wk * c1 : 0.0f;

        // Warp shuffle reductions (deterministic order)
        float rA0 = cA0, rA1 = cA1;
#pragma unroll
        for (int off = 16; off; off >>= 1) {
            rA0 += __shfl_down_sync(0xFFFFFFFFu, rA0, off);
            rA1 += __shfl_down_sync(0xFFFFFFFFu, rA1, off);
        }
        unsigned bal = __ballot_sync(0xFFFFFFFFu, active);
        if (lane == 0) {
            s_wA0[wid] = rA0;
            s_wA1[wid] = rA1;
            s_wn[wid]  = __popc(bal);
        }
        __syncthreads();

        // Everyone computes totals from the 4 warp partials (cheap, uniform)
        float A0 = (s_wA0[0] + s_wA0[1]) + (s_wA0[2] + s_wA0[3]);
        float A1 = (s_wA1[0] + s_wA1[1]) + (s_wA1[2] + s_wA1[3]);
        int nbefore = 0;
#pragma unroll
        for (int q = 0; q < 4; ++q) nbefore += (q < wid) ? s_wn[q] : 0;
        int ntot = s_wn[0] + s_wn[1] + s_wn[2] + s_wn[3];

        if (k == 0) {
            g_A0[mlp][m] = A0;
            g_A1[mlp][m] = A1;
            g_nact[mlp][m] = ntot;
            // Constant-fill detection: nact==0 -> o(i) affine -> monotone
            // through the (identical) epilogue; equal endpoints => constant.
            int isfill = 0;
            float fv = 0.0f;
            if (ntot == 0) {
                float oa = fmaf((float)s0, A1, A0);
                float ob = fmaf((float)(s1 - 1), A1, A0);
                float ca = coord_of(oa, b3);
                float cb = coord_of(ob, b3);
                if (ca == cb) { isfill = 1; fv = ca; }
            }
            g_isfill[mlp][m] = isfill;
            g_fill[mlp][m]   = fv;
        }

        if (active) {
            int idx = nbefore + __popc(bal & ((1u << lane) - 1u));
            g_ac0[mlp][m][idx] = c0;
            g_ac1[mlp][m][idx] = c1;
            g_awk[mlp][m][idx] = wk;
        }
    }
}

// ---------------------------------------------------------------------------
// Main kernel: grid (NROWS/(TPB*RPT), 2), 256 threads, 8 rows/thread.
// Constant segments -> pure stores; otherwise affine + tiny active list.
// ---------------------------------------------------------------------------
__global__ void __launch_bounds__(TPB) main_kernel(
    const float* __restrict__ gb3, const float* __restrict__ rb3,
    float* __restrict__ out)
{
    __shared__ float s_ac0[H], s_ac1[H], s_awk[H];
    __shared__ int   s_B[NB];
    __shared__ float s_A0, s_A1, s_b3, s_fill;
    __shared__ int   s_nact, s_isfill;

    const int tid = threadIdx.x;
    const int mlp = blockIdx.y;

    for (int q = tid; q < NB; q += TPB) s_B[q] = g_B[mlp][q];
    if (tid == 0) s_b3 = (mlp ? rb3 : gb3)[0];
    __syncthreads();

    const int r0   = blockIdx.x * (TPB * RPT);
    const int rend = r0 + TPB * RPT;
    const int i0   = r0 + tid * RPT;
    const float fi0 = (float)i0;
    const float b3 = s_b3;
    float* outp = out + mlp * NROWS;

    // Binary search: largest cur in [0, NSEG-1] with s_B[cur] <= r0.
    // (Duplicate boundaries = empty segments are skipped automatically.)
    int lo = 0, hi = NSEG - 1;
    while (lo < hi) {
        int mid = (lo + hi + 1) >> 1;
        if (s_B[mid] <= r0) lo = mid; else hi = mid - 1;
    }
    int cur = lo;

    int segS = r0;
    while (segS < rend) {
        while (cur < NSEG - 1 && s_B[cur + 1] <= segS) ++cur;  // few steps
        int segE = min(s_B[cur + 1], rend);
        if (segE <= segS) segE = rend;                         // safety

        __syncthreads();                     // previous segment reads done
        if (tid == 0) {
            s_A0 = g_A0[mlp][cur];
            s_A1 = g_A1[mlp][cur];
            s_nact = g_nact[mlp][cur];
            s_isfill = g_isfill[mlp][cur];
            s_fill = g_fill[mlp][cur];
        }
        if (tid < H) {
            s_ac0[tid] = g_ac0[mlp][cur][tid];
            s_ac1[tid] = g_ac1[mlp][cur][tid];
            s_awk[tid] = g_awk[mlp][cur][tid];
        }
        __syncthreads();

        if (i0 < segE && i0 + RPT > segS) {
            if (s_isfill) {
                const float fv = s_fill;
                if (i0 >= segS && i0 + RPT <= segE) {
                    float4 f4 = make_float4(fv, fv, fv, fv);
                    *(float4*)(outp + i0)     = f4;
                    *(float4*)(outp + i0 + 4) = f4;
                } else {
#pragma unroll
                    for (int rr = 0; rr < RPT; ++rr) {
                        int ii = i0 + rr;
                        if (ii >= segS && ii < segE) outp[ii] = fv;
                    }
                }
            } else {
                const float A0 = s_A0, A1 = s_A1;
                const int nact = s_nact;     // block-uniform
                float v[RPT];
#pragma unroll
                for (int rr = 0; rr < RPT; ++rr) {
                    const float fi = fi0 + (float)rr;
                    float o = fmaf(fi, A1, A0);
                    for (int j = 0; j < nact; ++j) {
                        float x = fmaf(fi, s_ac1[j], s_ac0[j]);
                        float e = fmaxf(x, -1.0f);
                        if (x < 0.0f && x > NEG_CUT) e = expm1f(x);
                        o = fmaf(s_awk[j], e, o);
                    }
                    v[rr] = coord_of(o, b3);
                }
                if (i0 >= segS && i0 + RPT <= segE) {
                    *(float4*)(outp + i0)     = make_float4(v[0], v[1], v[2], v[3]);
                    *(float4*)(outp + i0 + 4) = make_float4(v[4], v[5], v[6], v[7]);
                } else {
#pragma unroll
                    for (int rr = 0; rr < RPT; ++rr) {
                        int ii = i0 + rr;
                        if (ii >= segS && ii < segE) outp[ii] = v[rr];
                    }
                }
            }
        }
        segS = segE;
    }
}

// ---------------------------------------------------------------------------
// Host: size-signature input scan (elements, then bytes, then positional).
// ---------------------------------------------------------------------------
struct InMap {
    int z, gW1, gb1, gW2, gb2, gW3, gb3, rW1, rb1, rW2, rb2, rW3, rb3;
    bool ok;
};

static InMap scan_sizes(const int* in_sizes, int n_in, int unit)
{
    InMap m; m.ok = false;
    int i1792[2], n1792 = 0;
    int i16384[2], n16384 = 0;
    int i128[6], n128 = 0;
    int i1[2], n1 = 0;
    int iz = -1;

    const int S_W1 = 1792 * unit, S_W2 = 16384 * unit, S_128 = 128 * unit,
              S_1 = 1 * unit, S_Z = 10 * unit;

    for (int i = 0; i < n_in; ++i) {
        int s = in_sizes[i];
        if (s == S_W1 && n1792 < 2)        i1792[n1792++] = i;
        else if (s == S_W2 && n16384 < 2)  i16384[n16384++] = i;
        else if (s == S_128 && n128 < 6)   i128[n128++] = i;
        else if (s == S_1 && n1 < 2)       i1[n1++] = i;
        else if (s == S_Z && iz < 0)       iz = i;
    }
    if (n1792 != 2 || n16384 != 2 || n128 != 6 || n1 != 2 || iz < 0) return m;

    bool dict_order = i128[0] < i16384[0];

    m.z = iz;
    m.gW1 = i1792[0];  m.rW1 = i1792[1];
    m.gW2 = i16384[0]; m.rW2 = i16384[1];
    m.gb3 = i1[0];     m.rb3 = i1[1];
    if (dict_order) {
        m.gb1 = i128[0]; m.gb2 = i128[1]; m.gW3 = i128[2];
        m.rb1 = i128[3]; m.rb2 = i128[4]; m.rW3 = i128[5];
    } else {
        m.gW3 = i128[0]; m.gb1 = i128[1]; m.gb2 = i128[2];
        m.rW3 = i128[3]; m.rb1 = i128[4]; m.rb2 = i128[5];
    }
    m.ok = true;
    return m;
}

extern "C" void kernel_launch(void* const* d_in, const int* in_sizes, int n_in,
                              void* d_out, int out_size)
{
    InMap m = scan_sizes(in_sizes, n_in, 1);
    if (!m.ok) m = scan_sizes(in_sizes, n_in, 4);
    if (!m.ok) {
        m.z = 0;
        m.gW1 = 2;  m.gb1 = 3;  m.gW2 = 4;  m.gb2 = 5;  m.gW3 = 6;  m.gb3 = 7;
        m.rW1 = 8;  m.rb1 = 9;  m.rW2 = 10; m.rb2 = 11; m.rW3 = 12; m.rb3 = 13;
    }

    const float* z   = (const float*)d_in[m.z];
    const float* gW1 = (const float*)d_in[m.gW1];
    const float* gb1 = (const float*)d_in[m.gb1];
    const float* gW2 = (const float*)d_in[m.gW2];
    const float* gb2 = (const float*)d_in[m.gb2];
    const float* gW3 = (const float*)d_in[m.gW3];
    const float* gb3 = (const float*)d_in[m.gb3];
    const float* rW1 = (const float*)d_in[m.rW1];
    const float* rb1 = (const float*)d_in[m.rb1];
    const float* rW2 = (const float*)d_in[m.rW2];
    const float* rb2 = (const float*)d_in[m.rb2];
    const float* rW3 = (const float*)d_in[m.rW3];
    const float* rb3 = (const float*)d_in[m.rb3];

    float* out = (float*)d_out;
    int nmlp = (out_size >= 2 * NROWS) ? 2 : 1;

    prep_kernel<<<dim3(PREP_GRID, 2), H>>>(z, gW1, gb1, gW2, gb2, gW3, gb3,
                                           rW1, rb1, rW2, rb2, rW3, rb3);
    main_kernel<<<dim3(NROWS / (TPB * RPT), nmlp), TPB>>>(gb3, rb3, out);
}

// round 10
// speedup vs baseline: 97.5253x; 1.0135x over previous
#include <cuda_runtime.h>
#include <math.h>

#define NROWS 524288
#define H 128
#define NSEG 129          // max segments (128 layer-1 breakpoints + 1)
#define NB (NSEG + 1)     // boundary entries B[0..129]
#define TPB 256
#define RPT 4

// level_data is a module-level constant of the problem:
//   [GRID_SIZE=100, N_GREEN=524288, N_RED=524288]; scale = 100^2-1 = 9999.
#define LD0 100.0f
#define LD1 524288.0f
#define LD2 524288.0f
#define SCALE_CONST 9999.0f
#define NEG_CUT -18.0f    // for x <= -18: exp(x)-1 rounds to -1.0f exactly (fp32)

// Per-MLP, per-segment data (device globals: no allocations allowed)
__device__ float g_A0[2][NSEG];          // folded affine part
__device__ float g_A1[2][NSEG];
__device__ int   g_nact[2][NSEG];        // # active (non-foldable) units
__device__ int   g_isfill[2][NSEG];      // 1 -> constant segment
__device__ float g_fill[2][NSEG];        // the constant coord value
__device__ float g_ac0[2][NSEG][H];      // active-unit coefficients
__device__ float g_ac1[2][NSEG][H];
__device__ float g_awk[2][NSEG][H];
__device__ int   g_B[2][NB];             // segment boundaries

// Shared epilogue — identical instruction sequence in prep & main
__device__ __forceinline__ float coord_of(float o, float b3) {
    float t = (o + b3) * (1.0f / 500.0f);
    float sg = 1.0f / (1.0f + __expf(-t));
    return (float)(int)(sg * SCALE_CONST);
}

// Branchless ELU, exact vs reference within fp32 rounding for all x:
//   x >= 0            -> x
//   -18 < x < 0       -> __expf(x)-1  (fast exp; error ~1e-7 abs, negligible)
//   x <= -18          -> __expf(x)-1 == -1.0f exactly
__device__ __forceinline__ float elu_fast(float x) {
    float ex = __expf(fminf(x, 0.0f)) - 1.0f;
    return (x >= 0.0f) ? x : ex;
}

// ---------------------------------------------------------------------------
// Prep kernel: grid (NSEG, 2), 128 threads — ONE segment per block.
// ---------------------------------------------------------------------------
__global__ void __launch_bounds__(H) prep_kernel(
    const float* __restrict__ z,
    const float* __restrict__ gW1, const float* __restrict__ gb1,
    const float* __restrict__ gW2, const float* __restrict__ gb2,
    const float* __restrict__ gW3, const float* __restrict__ gb3,
    const float* __restrict__ rW1, const float* __restrict__ rb1,
    const float* __restrict__ rW2, const float* __restrict__ rb2,
    const float* __restrict__ rW3, const float* __restrict__ rb3)
{
    __shared__ float s_zext[16];
    __shared__ float s_sb[H], s_sw[H];
    __shared__ float s_wA0[4], s_wA1[4];
    __shared__ int   s_wn[4];
    __shared__ int   s_bk[H];
    __shared__ int   s_B[NB];

    const int k    = threadIdx.x;
    const int lane = k & 31;
    const int wid  = k >> 5;
    const int mlp  = blockIdx.y;
    const int m    = blockIdx.x;          // this block's segment
    const float* W1 = mlp ? rW1 : gW1;
    const float* b1 = mlp ? rb1 : gb1;
    const float* W2 = mlp ? rW2 : gW2;
    const float* b2 = mlp ? rb2 : gb2;
    const float* W3 = mlp ? rW3 : gW3;
    const float  b3 = (mlp ? rb3 : gb3)[0];

    if (k < 10) s_zext[k] = z[k];
    if (k == 10) s_zext[10] = LD0;
    if (k == 11) s_zext[11] = LD1;
    if (k == 12) s_zext[12] = LD2;
    __syncthreads();

    // Layer-1 affine form: pre_k(i) = base_k + i * w_k (exact: only idx varies)
    float base = b1[k];
#pragma unroll
    for (int j = 0; j < 13; ++j) base = fmaf(W1[k * 14 + j], s_zext[j], base);
    float w = W1[k * 14 + 13];

    // Integer breakpoint where LeakyReLU's slope flips (sentinel NROWS)
    int bk = NROWS;
    if (w != 0.0f) {
        float t = -base / w;
        if (t > 0.0f && t < (float)NROWS) {
            bk = (int)ceilf(t);
            if (bk < 1) bk = 1;
            if (bk > NROWS) bk = NROWS;
        }
    }
    s_bk[k] = bk;
    __syncthreads();

    // Rank sort -> sorted boundary list
    int r = 0;
#pragma unroll 8
    for (int j = 0; j < H; ++j) {
        int v = s_bk[j];
        r += (v < bk) || (v == bk && j < k);
    }
    if (k == 0) { s_B[0] = 0; s_B[NB - 1] = NROWS; }
    s_B[1 + r] = bk;
    __syncthreads();

    if (m == 0) {
        for (int q = k; q < NB; q += H) g_B[mlp][q] = s_B[q];
    }

    const int s0 = s_B[m], s1 = s_B[m + 1];
    if (s0 >= s1) return;                 // empty segment: main never reads it

    // leaky_relu slope is constant within the segment; probe i=s0
    {
        float pre = fmaf((float)s0, w, base);
        float sl  = (pre >= 0.0f) ? 1.0f : 0.2f;
        s_sb[k] = sl * base;
        s_sw[k] = sl * w;
    }
    __syncthreads();

    const float4* W2v = (const float4*)(W2 + k * H);
    const float wk = W3[k];
    float c0 = b2[k], c1 = 0.0f;
#pragma unroll 4
    for (int jv = 0; jv < H / 4; ++jv) {
        float4 wv = __ldg(&W2v[jv]);
        int j = jv * 4;
        c0 = fmaf(wv.x, s_sb[j + 0], c0);  c1 = fmaf(wv.x, s_sw[j + 0], c1);
        c0 = fmaf(wv.y, s_sb[j + 1], c0);  c1 = fmaf(wv.y, s_sw[j + 1], c1);
        c0 = fmaf(wv.z, s_sb[j + 2], c0);  c1 = fmaf(wv.z, s_sw[j + 2], c1);
        c0 = fmaf(wv.w, s_sb[j + 3], c0);  c1 = fmaf(wv.w, s_sw[j + 3], c1);
    }

    // Classify over i in [s0, s1-1]: x(i)=RN(c0+i*c1) is monotone in i.
    float xa = fmaf((float)s0, c1, c0);
    float xb = fmaf((float)(s1 - 1), c1, c0);
    float lo = fminf(xa, xb), hi = fmaxf(xa, xb);
    bool lin = (lo >= 0.0f);          // elu(x)=x exactly
    bool neg = (hi <= NEG_CUT);       // elu(x)=-1 exactly in fp32
    int active = (!lin && !neg) ? 1 : 0;

    float cA0 = lin ? wk * c0 : (neg ? -wk : 0.0f);
    float cA1 = lin ? wk * c1 : 0.0f;

    // Warp shuffle reductions (deterministic order)
    float rA0 = cA0, rA1 = cA1;
#pragma unroll
    for (int off = 16; off; off >>= 1) {
        rA0 += __shfl_down_sync(0xFFFFFFFFu, rA0, off);
        rA1 += __shfl_down_sync(0xFFFFFFFFu, rA1, off);
    }
    unsigned bal = __ballot_sync(0xFFFFFFFFu, active);
    if (lane == 0) {
        s_wA0[wid] = rA0;
        s_wA1[wid] = rA1;
        s_wn[wid]  = __popc(bal);
    }
    __syncthreads();

    float A0 = (s_wA0[0] + s_wA0[1]) + (s_wA0[2] + s_wA0[3]);
    float A1 = (s_wA1[0] + s_wA1[1]) + (s_wA1[2] + s_wA1[3]);
    int nbefore = 0;
#pragma unroll
    for (int q = 0; q < 4; ++q) nbefore += (q < wid) ? s_wn[q] : 0;
    int ntot = s_wn[0] + s_wn[1] + s_wn[2] + s_wn[3];

    if (k == 0) {
        g_A0[mlp][m] = A0;
        g_A1[mlp][m] = A1;
        g_nact[mlp][m] = ntot;
        // Constant-fill: nact==0 -> o(i) affine -> monotone through the
        // identical epilogue; equal endpoint coords => constant segment.
        int isfill = 0;
        float fv = 0.0f;
        if (ntot == 0) {
            float oa = fmaf((float)s0, A1, A0);
            float ob = fmaf((float)(s1 - 1), A1, A0);
            float ca = coord_of(oa, b3);
            float cb = coord_of(ob, b3);
            if (ca == cb) { isfill = 1; fv = ca; }
        }
        g_isfill[mlp][m] = isfill;
        g_fill[mlp][m]   = fv;
    }

    if (active) {
        int idx = nbefore + __popc(bal & ((1u << lane) - 1u));
        g_ac0[mlp][m][idx] = c0;
        g_ac1[mlp][m][idx] = c1;
        g_awk[mlp][m][idx] = wk;
    }
}

// ---------------------------------------------------------------------------
// Main kernel: grid (NROWS/(TPB*RPT), 2), 256 threads, 4 rows/thread.
// ---------------------------------------------------------------------------
__global__ void __launch_bounds__(TPB) main_kernel(
    const float* __restrict__ gb3, const float* __restrict__ rb3,
    float* __restrict__ out)
{
    __shared__ float s_ac0[H], s_ac1[H], s_awk[H];
    __shared__ int   s_B[NB];
    __shared__ float s_A0, s_A1, s_b3, s_fill;
    __shared__ int   s_nact;

    const int tid = threadIdx.x;
    const int mlp = blockIdx.y;

    for (int q = tid; q < NB; q += TPB) s_B[q] = g_B[mlp][q];
    if (tid == 0) s_b3 = (mlp ? rb3 : gb3)[0];
    __syncthreads();

    const int r0   = blockIdx.x * (TPB * RPT);
    const int rend = r0 + TPB * RPT;
    const int i0   = r0 + tid * RPT;
    const float fi0 = (float)i0;
    const float b3 = s_b3;
    float* outp = out + mlp * NROWS;

    // Binary search: largest cur with s_B[cur] <= r0.
    int lo = 0, hi = NSEG - 1;
    while (lo < hi) {
        int mid = (lo + hi + 1) >> 1;
        if (s_B[mid] <= r0) lo = mid; else hi = mid - 1;
    }
    int cur = lo;

    int segS = r0;
    while (segS < rend) {
        while (cur < NSEG - 1 && s_B[cur + 1] <= segS) ++cur;
        int segE = min(s_B[cur + 1], rend);
        if (segE <= segS) segE = rend;                         // safety

        // Broadcast flag read (L1-cached, uniform) decides the load set.
        const int isfill = g_isfill[mlp][cur];

        __syncthreads();                     // previous segment reads done
        if (isfill) {
            if (tid == 0) s_fill = g_fill[mlp][cur];
        } else {
            if (tid == 0) {
                s_A0 = g_A0[mlp][cur];
                s_A1 = g_A1[mlp][cur];
                s_nact = g_nact[mlp][cur];
            }
            if (tid < H) {
                s_ac0[tid] = g_ac0[mlp][cur][tid];
                s_ac1[tid] = g_ac1[mlp][cur][tid];
                s_awk[tid] = g_awk[mlp][cur][tid];
            }
        }
        __syncthreads();

        if (i0 < segE && i0 + RPT > segS) {
            if (isfill) {
                const float fv = s_fill;
                if (i0 >= segS && i0 + RPT <= segE) {
                    *(float4*)(outp + i0) = make_float4(fv, fv, fv, fv);
                } else {
#pragma unroll
                    for (int rr = 0; rr < RPT; ++rr) {
                        int ii = i0 + rr;
                        if (ii >= segS && ii < segE) outp[ii] = fv;
                    }
                }
            } else {
                const float A0 = s_A0, A1 = s_A1;
                const int nact = s_nact;     // block-uniform
                float v[RPT];
#pragma unroll
                for (int rr = 0; rr < RPT; ++rr) {
                    const float fi = fi0 + (float)rr;
                    float o = fmaf(fi, A1, A0);
                    for (int j = 0; j < nact; ++j) {
                        float x = fmaf(fi, s_ac1[j], s_ac0[j]);
                        o = fmaf(s_awk[j], elu_fast(x), o);
                    }
                    v[rr] = coord_of(o, b3);
                }
                if (i0 >= segS && i0 + RPT <= segE) {
                    *(float4*)(outp + i0) = make_float4(v[0], v[1], v[2], v[3]);
                } else {
#pragma unroll
                    for (int rr = 0; rr < RPT; ++rr) {
                        int ii = i0 + rr;
                        if (ii >= segS && ii < segE) outp[ii] = v[rr];
                    }
                }
            }
        }
        segS = segE;
    }
}

// ---------------------------------------------------------------------------
// Host: size-signature input scan (elements, then bytes, then positional).
// ---------------------------------------------------------------------------
struct InMap {
    int z, gW1, gb1, gW2, gb2, gW3, gb3, rW1, rb1, rW2, rb2, rW3, rb3;
    bool ok;
};

static InMap scan_sizes(const int* in_sizes, int n_in, int unit)
{
    InMap m; m.ok = false;
    int i1792[2], n1792 = 0;
    int i16384[2], n16384 = 0;
    int i128[6], n128 = 0;
    int i1[2], n1 = 0;
    int iz = -1;

    const int S_W1 = 1792 * unit, S_W2 = 16384 * unit, S_128 = 128 * unit,
              S_1 = 1 * unit, S_Z = 10 * unit;

    for (int i = 0; i < n_in; ++i) {
        int s = in_sizes[i];
        if (s == S_W1 && n1792 < 2)        i1792[n1792++] = i;
        else if (s == S_W2 && n16384 < 2)  i16384[n16384++] = i;
        else if (s == S_128 && n128 < 6)   i128[n128++] = i;
        else if (s == S_1 && n1 < 2)       i1[n1++] = i;
        else if (s == S_Z && iz < 0)       iz = i;
    }
    if (n1792 != 2 || n16384 != 2 || n128 != 6 || n1 != 2 || iz < 0) return m;

    bool dict_order = i128[0] < i16384[0];

    m.z = iz;
    m.gW1 = i1792[0];  m.rW1 = i1792[1];
    m.gW2 = i16384[0]; m.rW2 = i16384[1];
    m.gb3 = i1[0];     m.rb3 = i1[1];
    if (dict_order) {
        m.gb1 = i128[0]; m.gb2 = i128[1]; m.gW3 = i128[2];
        m.rb1 = i128[3]; m.rb2 = i128[4]; m.rW3 = i128[5];
    } else {
        m.gW3 = i128[0]; m.gb1 = i128[1]; m.gb2 = i128[2];
        m.rW3 = i128[3]; m.rb1 = i128[4]; m.rb2 = i128[5];
    }
    m.ok = true;
    return m;
}

extern "C" void kernel_launch(void* const* d_in, const int* in_sizes, int n_in,
                              void* d_out, int out_size)
{
    InMap m = scan_sizes(in_sizes, n_in, 1);
    if (!m.ok) m = scan_sizes(in_sizes, n_in, 4);
    if (!m.ok) {
        m.z = 0;
        m.gW1 = 2;  m.gb1 = 3;  m.gW2 = 4;  m.gb2 = 5;  m.gW3 = 6;  m.gb3 = 7;
        m.rW1 = 8;  m.rb1 = 9;  m.rW2 = 10; m.rb2 = 11; m.rW3 = 12; m.rb3 = 13;
    }

    const float* z   = (const float*)d_in[m.z];
    const float* gW1 = (const float*)d_in[m.gW1];
    const float* gb1 = (const float*)d_in[m.gb1];
    const float* gW2 = (const float*)d_in[m.gW2];
    const float* gb2 = (const float*)d_in[m.gb2];
    const float* gW3 = (const float*)d_in[m.gW3];
    const float* gb3 = (const float*)d_in[m.gb3];
    const float* rW1 = (const float*)d_in[m.rW1];
    const float* rb1 = (const float*)d_in[m.rb1];
    const float* rW2 = (const float*)d_in[m.rW2];
    const float* rb2 = (const float*)d_in[m.rb2];
    const float* rW3 = (const float*)d_in[m.rW3];
    const float* rb3 = (const float*)d_in[m.rb3];

    float* out = (float*)d_out;
    int nmlp = (out_size >= 2 * NROWS) ? 2 : 1;

    prep_kernel<<<dim3(NSEG, 2), H>>>(z, gW1, gb1, gW2, gb2, gW3, gb3,
                                      rW1, rb1, rW2, rb2, rW3, rb3);
    main_kernel<<<dim3(NROWS / (TPB * RPT), nmlp), TPB>>>(gb3, rb3, out);
}